// round 8
// baseline (speedup 1.0000x reference)
#include <cuda_runtime.h>
#include <cuda_bf16.h>
#include <stdint.h>
#include <math.h>

#define NB 8
#define NC 64
#define NN 4000
#define TI 128          // i-tile
#define TJ 64           // j-tile
#define JT63 63         // ceil(4000/64) j-tiles per mode
#define IT32 32         // ceil(4000/128) i-tiles
#define TOTAL_BLOCKS (2 * JT63 * IT32 * NB)
#define SMSTRIDE 72     // 64 bf16 + 8 pad (144B rows; ldmatrix conflict-free)

// Scratch (device globals; no allocations allowed)
__device__ __nv_bfloat16 g_feat2[NB * NN * NC];  // normalized, COMPACTED order
__device__ int           g_pmap[NB * NN];
__device__ int           g_cnt[NB];
__device__ double        g_pos[NB];
__device__ double        g_neg[NB];
__device__ unsigned      g_done;                 // completion counter (self-resetting)

// ---------------------------------------------------------------------------
// Kernel 1: classify + position map (deterministic), init accumulators.
// ---------------------------------------------------------------------------
__global__ void compact_kernel(const float* __restrict__ prob) {
    int b = blockIdx.x;
    int tid = threadIdx.x;
    __shared__ int wtN[8], wtA[8];
    __shared__ int baseN, baseA;
    if (tid == 0) { baseN = 0; baseA = 0; }
    __syncthreads();

    for (int c0 = 0; c0 < NN; c0 += 256) {
        int idx = c0 + tid;
        bool inr = idx < NN;
        bool nrm = false;
        if (inr) nrm = prob[b * NN + idx] < 0.5f;
        bool ano = inr && !nrm;
        unsigned mN = __ballot_sync(0xffffffffu, nrm);
        unsigned mA = __ballot_sync(0xffffffffu, ano);
        int lane = tid & 31, wid = tid >> 5;
        unsigned below = (1u << lane) - 1u;
        int pN = __popc(mN & below), pA = __popc(mA & below);
        if (lane == 0) { wtN[wid] = __popc(mN); wtA[wid] = __popc(mA); }
        __syncthreads();
        int oN = 0, oA = 0, tN = 0, tA = 0;
        for (int w = 0; w < 8; w++) {
            if (w < wid) { oN += wtN[w]; oA += wtA[w]; }
            tN += wtN[w]; tA += wtA[w];
        }
        if (nrm) g_pmap[b * NN + idx] = baseN + oN + pN;
        if (ano) g_pmap[b * NN + idx] = ~(baseA + oA + pA);
        __syncthreads();
        if (tid == 0) { baseN += tN; baseA += tA; }
        __syncthreads();
    }
    if (tid == 0) {
        g_cnt[b] = baseN;
        g_pos[b] = 0.0;
        g_neg[b] = 0.0;
    }
}

// ---------------------------------------------------------------------------
// Kernel 2: row-normalize (fp32) -> bf16, writing to COMPACTED row position.
// ---------------------------------------------------------------------------
__global__ void normalize_kernel(const float* __restrict__ feat) {
    int row = blockIdx.x * blockDim.x + threadIdx.x;
    if (row >= NB * NN) return;
    int b = row / NN;
    int n = row - b * NN;
    const float* src = feat + (size_t)b * NC * NN + n;
    float v[NC];
    float ss = 0.f;
#pragma unroll
    for (int c = 0; c < NC; c++) {
        float x = src[(size_t)c * NN];
        v[c] = x;
        ss += x * x;
    }
    float inv = 1.0f / fmaxf(sqrtf(ss), 1e-12f);
    int pm = g_pmap[b * NN + n];
    int dstRow = (pm >= 0) ? pm : (g_cnt[b] + ~pm);
    __nv_bfloat16* dst = g_feat2 + ((size_t)b * NN + dstRow) * NC;
#pragma unroll
    for (int c = 0; c < NC; c++) dst[c] = __float2bfloat16(v[c] * inv);
}

// ---------------------------------------------------------------------------
// Fused GEMM + loss + inline finalize (last block).
// mode 0: normal x normal upper triangle (cj > ri), sum exp, x2.
// mode 1: normal x anomaly (softplus).
// ---------------------------------------------------------------------------
__device__ __forceinline__ void cpa16(unsigned dst, const void* src, bool valid) {
    int sz = valid ? 16 : 0;
    asm volatile("cp.async.cg.shared.global [%0], [%1], 16, %2;\n"
                 :: "r"(dst), "l"(src), "r"(sz));
}
__device__ __forceinline__ void ldm_x4(unsigned r[4], unsigned addr) {
    asm volatile("ldmatrix.sync.aligned.m8n8.x4.shared.b16 {%0,%1,%2,%3}, [%4];\n"
                 : "=r"(r[0]), "=r"(r[1]), "=r"(r[2]), "=r"(r[3]) : "r"(addr));
}
__device__ __forceinline__ void mma_bf16(float d[4], const unsigned a[4],
                                         unsigned b0, unsigned b1) {
    asm volatile(
        "mma.sync.aligned.m16n8k16.row.col.f32.bf16.bf16.f32 "
        "{%0,%1,%2,%3}, {%4,%5,%6,%7}, {%8,%9}, {%0,%1,%2,%3};\n"
        : "+f"(d[0]), "+f"(d[1]), "+f"(d[2]), "+f"(d[3])
        : "r"(a[0]), "r"(a[1]), "r"(a[2]), "r"(a[3]), "r"(b0), "r"(b1));
}

__global__ __launch_bounds__(256, 4) void mma_loss_kernel(float* __restrict__ out) {
    int b = blockIdx.z;
    int nI = g_cnt[b];
    int mode = (blockIdx.x >= JT63) ? 1 : 0;
    int jt = blockIdx.x - mode * JT63;
    int nJ = mode ? (NN - nI) : nI;
    int i0 = blockIdx.y * TI;
    int j0 = jt * TJ;

    __shared__ __nv_bfloat16 As[TI][SMSTRIDE];
    __shared__ __nv_bfloat16 Bs[TJ][SMSTRIDE];
    __shared__ float s_warp[8];
    __shared__ int s_last;

    int tid = threadIdx.x;
    int warp = tid >> 5, lane = tid & 31;

    bool active = (i0 < nI) && (j0 < nJ) &&
                  !(mode == 0 && (j0 + TJ - 1) <= i0);

    if (active) {
        const __nv_bfloat16* Abase = g_feat2 + ((size_t)b * NN + i0) * NC;
        const __nv_bfloat16* Bbase =
            g_feat2 + ((size_t)b * NN + (mode ? nI : 0) + j0) * NC;

#pragma unroll
        for (int c = 0; c < 4; c++) {
            int chunk = tid + c * 256;
            int r = chunk >> 3, col = chunk & 7;
            unsigned dst = (unsigned)__cvta_generic_to_shared(&As[r][col * 8]);
            cpa16(dst, Abase + (size_t)r * NC + col * 8, (i0 + r) < nI);
        }
#pragma unroll
        for (int c = 0; c < 2; c++) {
            int chunk = tid + c * 256;
            int r = chunk >> 3, col = chunk & 7;
            unsigned dst = (unsigned)__cvta_generic_to_shared(&Bs[r][col * 8]);
            cpa16(dst, Bbase + (size_t)r * NC + col * 8, (j0 + r) < nJ);
        }
        asm volatile("cp.async.commit_group;\n");
        asm volatile("cp.async.wait_group 0;\n");
        __syncthreads();

        int mBase = warp * 16;               // warp tile 16 (M) x 64 (N)
        float acc[8][4];
#pragma unroll
        for (int ni = 0; ni < 8; ni++)
#pragma unroll
            for (int e = 0; e < 4; e++) acc[ni][e] = 0.f;

#pragma unroll
        for (int ks = 0; ks < 4; ks++) {
            int k0 = ks * 16;
            unsigned afr[4];
            {
                unsigned a = (unsigned)__cvta_generic_to_shared(
                    &As[mBase + (lane & 15)][k0 + (lane >> 4) * 8]);
                ldm_x4(afr, a);
            }
#pragma unroll
            for (int np = 0; np < 4; np++) {
                unsigned bt[4];
                unsigned a = (unsigned)__cvta_generic_to_shared(
                    &Bs[np * 16 + (lane & 7) + 8 * (lane >> 4)]
                       [k0 + ((lane >> 3) & 1) * 8]);
                ldm_x4(bt, a);
                mma_bf16(acc[np * 2 + 0], afr, bt[0], bt[1]);
                mma_bf16(acc[np * 2 + 1], afr, bt[2], bt[3]);
            }
        }

        const float K10LOG2E = 14.4269504089f;
        int g = lane >> 2, tq = lane & 3;
        int riB = i0 + mBase + g;
        int cjB = j0 + tq * 2;
        float sumv = 0.f;
#pragma unroll
        for (int ni = 0; ni < 8; ni++) {
#pragma unroll
            for (int e = 0; e < 4; e++) {
                int ri = riB + ((e >> 1) ? 8 : 0);
                int cj = cjB + ni * 8 + (e & 1);
                if (ri >= nI || cj >= nJ) continue;
                if (mode == 0) {
                    if (cj > ri) sumv += exp2f(acc[ni][e] * K10LOG2E);
                } else {
                    float ex = exp2f(acc[ni][e] * K10LOG2E);
                    sumv += __log2f(1.0f + ex);
                }
            }
        }

#pragma unroll
        for (int o = 16; o; o >>= 1)
            sumv += __shfl_down_sync(0xffffffffu, sumv, o);
        if (lane == 0) s_warp[warp] = sumv;
        __syncthreads();
        if (warp == 0) {
            float v = (lane < 8) ? s_warp[lane] : 0.f;
#pragma unroll
            for (int o = 4; o; o >>= 1)
                v += __shfl_down_sync(0xffffffffu, v, o);
            if (lane == 0) {
                if (mode == 0) atomicAdd(&g_pos[b], 2.0 * (double)v);
                else atomicAdd(&g_neg[b], (double)v * 0.6931471805599453);
            }
        }
    }

    // Completion protocol: EVERY block (active or not) arrives once.
    __syncthreads();
    if (tid == 0) {
        __threadfence();
        unsigned t = atomicAdd(&g_done, 1u);
        s_last = (t == (unsigned)(TOTAL_BLOCKS - 1)) ? 1 : 0;
    }
    __syncthreads();

    if (s_last) {
        if (tid == 0) {
            __threadfence();     // acquire all g_pos/g_neg before reading
            g_done = 0;          // self-reset for next graph replay
        }
        __syncthreads();
        if (warp == 0) {
            double per = 0.0, vcnt = 0.0;
            if (lane < NB) {
                int nn = g_cnt[lane];
                int na = NN - nn;
                bool valid = (nn >= 10) && (na >= 5);
                double pc = (double)nn * (double)nn - (double)nn;
                double cc = (double)nn * (double)na;
                double pm = g_pos[lane] / (pc > 1.0 ? pc : 1.0);
                double pl = -log(pm + 1e-6);
                double nl = g_neg[lane] / (cc > 1.0 ? cc : 1.0);
                if (valid) { per = pl + nl; vcnt = 1.0; }
            }
#pragma unroll
            for (int o = 16; o; o >>= 1) {
                per += __shfl_down_sync(0xffffffffu, per, o);
                vcnt += __shfl_down_sync(0xffffffffu, vcnt, o);
            }
            if (lane == 0) out[0] = (float)(per / (vcnt > 1.0 ? vcnt : 1.0));
        }
    }
}

extern "C" void kernel_launch(void* const* d_in, const int* in_sizes, int n_in,
                              void* d_out, int out_size) {
    const float* feat = (const float*)d_in[0];   // [8,64,4000,1]
    const float* prob = (const float*)d_in[1];   // [8,1,4000,1]

    compact_kernel<<<NB, 256>>>(prob);
    normalize_kernel<<<(NB * NN + 255) / 256, 256>>>(feat);
    dim3 grid(2 * JT63, IT32, NB);   // (mode|jt, it, b)
    mma_loss_kernel<<<grid, 256>>>((float*)d_out);
}

// round 9
// speedup vs baseline: 1.2847x; 1.2847x over previous
#include <cuda_runtime.h>
#include <cuda_bf16.h>
#include <stdint.h>
#include <math.h>

#define NB 8
#define NC 64
#define NN 4000
#define TI 128          // i-tile
#define TJ 64           // j-tile
#define JT63 63         // ceil(4000/64) j-tiles per mode
#define SMSTRIDE 72     // 64 bf16 + 8 pad (144B rows; ldmatrix conflict-free)
#define PER 16          // indices per thread in compact (256*16 = 4096 >= NN)

// Scratch (device globals; no allocations allowed)
__device__ __nv_bfloat16 g_feat2[NB * NN * NC];  // normalized, COMPACTED order
__device__ int           g_pmap[NB * NN];        // orig idx -> p (normal) or ~pA (anomaly)
__device__ int           g_cnt[NB];
__device__ double        g_pos[NB];
__device__ double        g_neg[NB];

// ---------------------------------------------------------------------------
// Kernel 1: classify + position map via ONE block-scan (deterministic).
// Thread t owns indices [t*16, t*16+16); predicates held in a bitmask.
// ---------------------------------------------------------------------------
__global__ void compact_kernel(const float* __restrict__ prob) {
    int b = blockIdx.x;
    int tid = threadIdx.x;
    int lane = tid & 31, wid = tid >> 5;
    int start = tid * PER;

    const float* pb = prob + b * NN;
    unsigned mask = 0;
    int cN = 0;
#pragma unroll
    for (int k = 0; k < PER; k++) {
        int idx = start + k;
        if (idx < NN && pb[idx] < 0.5f) { mask |= (1u << k); cN++; }
    }
    int nv = (start < NN) ? min(PER, NN - start) : 0;   // valid count in range
    int cA = nv - cN;

    // Warp-inclusive scan of (cN, cA)
    int sNi = cN, sAi = cA;
#pragma unroll
    for (int o = 1; o < 32; o <<= 1) {
        int xn = __shfl_up_sync(0xffffffffu, sNi, o);
        int xa = __shfl_up_sync(0xffffffffu, sAi, o);
        if (lane >= o) { sNi += xn; sAi += xa; }
    }
    __shared__ int wN[8], wA[8];
    if (lane == 31) { wN[wid] = sNi; wA[wid] = sAi; }
    __syncthreads();
    int baseWN = 0, baseWA = 0, totN = 0;
    for (int w = 0; w < 8; w++) {
        if (w < wid) { baseWN += wN[w]; baseWA += wA[w]; }
        totN += wN[w];
    }
    int offN = baseWN + sNi - cN;       // exclusive prefix for this thread
    int offA = baseWA + sAi - cA;

    int* pm = g_pmap + b * NN;
#pragma unroll
    for (int k = 0; k < PER; k++) {
        int idx = start + k;
        if (idx >= NN) break;
        if (mask & (1u << k)) pm[idx] = offN++;
        else                  pm[idx] = ~(offA++);
    }
    if (tid == 0) {
        g_cnt[b] = totN;
        g_pos[b] = 0.0;
        g_neg[b] = 0.0;
    }
}

// ---------------------------------------------------------------------------
// Kernel 2: row-normalize (fp32) -> bf16, writing to COMPACTED row position.
// ---------------------------------------------------------------------------
__global__ void normalize_kernel(const float* __restrict__ feat) {
    int row = blockIdx.x * blockDim.x + threadIdx.x;
    if (row >= NB * NN) return;
    int b = row / NN;
    int n = row - b * NN;
    const float* src = feat + (size_t)b * NC * NN + n;
    float v[NC];
    float ss = 0.f;
#pragma unroll
    for (int c = 0; c < NC; c++) {
        float x = src[(size_t)c * NN];
        v[c] = x;
        ss += x * x;
    }
    float inv = 1.0f / fmaxf(sqrtf(ss), 1e-12f);
    int pm = g_pmap[b * NN + n];
    int dstRow = (pm >= 0) ? pm : (g_cnt[b] + ~pm);
    __nv_bfloat16* dst = g_feat2 + ((size_t)b * NN + dstRow) * NC;
#pragma unroll
    for (int c = 0; c < NC; c++) dst[c] = __float2bfloat16(v[c] * inv);
}

// ---------------------------------------------------------------------------
// Merged fused GEMM + loss (R7-proven config).
// mode 0: normal x normal, UPPER TRIANGLE ONLY (cj > ri), sum exp, x2 at end.
// mode 1: normal x anomaly (softplus).
// Tile 128x64, 8 warps in M, warp tile 16x64. cp.async tile fills.
// ---------------------------------------------------------------------------
__device__ __forceinline__ void cpa16(unsigned dst, const void* src, bool valid) {
    int sz = valid ? 16 : 0;
    asm volatile("cp.async.cg.shared.global [%0], [%1], 16, %2;\n"
                 :: "r"(dst), "l"(src), "r"(sz));
}
__device__ __forceinline__ void ldm_x4(unsigned r[4], unsigned addr) {
    asm volatile("ldmatrix.sync.aligned.m8n8.x4.shared.b16 {%0,%1,%2,%3}, [%4];\n"
                 : "=r"(r[0]), "=r"(r[1]), "=r"(r[2]), "=r"(r[3]) : "r"(addr));
}
__device__ __forceinline__ void mma_bf16(float d[4], const unsigned a[4],
                                         unsigned b0, unsigned b1) {
    asm volatile(
        "mma.sync.aligned.m16n8k16.row.col.f32.bf16.bf16.f32 "
        "{%0,%1,%2,%3}, {%4,%5,%6,%7}, {%8,%9}, {%0,%1,%2,%3};\n"
        : "+f"(d[0]), "+f"(d[1]), "+f"(d[2]), "+f"(d[3])
        : "r"(a[0]), "r"(a[1]), "r"(a[2]), "r"(a[3]), "r"(b0), "r"(b1));
}

__global__ __launch_bounds__(256, 3) void mma_loss_kernel() {
    int b = blockIdx.z;
    int nI = g_cnt[b];
    int mode = (blockIdx.x >= JT63) ? 1 : 0;
    int jt = blockIdx.x - mode * JT63;
    int nJ = mode ? (NN - nI) : nI;
    int i0 = blockIdx.y * TI;
    int j0 = jt * TJ;
    if (i0 >= nI || j0 >= nJ) return;
    if (mode == 0 && (j0 + TJ - 1) <= i0) return;   // below diagonal: skip

    __shared__ __nv_bfloat16 As[TI][SMSTRIDE];
    __shared__ __nv_bfloat16 Bs[TJ][SMSTRIDE];
    __shared__ float s_warp[8];

    int tid = threadIdx.x;
    const __nv_bfloat16* Abase = g_feat2 + ((size_t)b * NN + i0) * NC;
    const __nv_bfloat16* Bbase =
        g_feat2 + ((size_t)b * NN + (mode ? nI : 0) + j0) * NC;

#pragma unroll
    for (int c = 0; c < 4; c++) {
        int chunk = tid + c * 256;
        int r = chunk >> 3, col = chunk & 7;
        unsigned dst = (unsigned)__cvta_generic_to_shared(&As[r][col * 8]);
        cpa16(dst, Abase + (size_t)r * NC + col * 8, (i0 + r) < nI);
    }
#pragma unroll
    for (int c = 0; c < 2; c++) {
        int chunk = tid + c * 256;
        int r = chunk >> 3, col = chunk & 7;
        unsigned dst = (unsigned)__cvta_generic_to_shared(&Bs[r][col * 8]);
        cpa16(dst, Bbase + (size_t)r * NC + col * 8, (j0 + r) < nJ);
    }
    asm volatile("cp.async.commit_group;\n");
    asm volatile("cp.async.wait_group 0;\n");
    __syncthreads();

    int warp = tid >> 5, lane = tid & 31;
    int mBase = warp * 16;               // warp tile 16 (M) x 64 (N)

    float acc[8][4];
#pragma unroll
    for (int ni = 0; ni < 8; ni++)
#pragma unroll
        for (int e = 0; e < 4; e++) acc[ni][e] = 0.f;

#pragma unroll
    for (int ks = 0; ks < 4; ks++) {
        int k0 = ks * 16;
        unsigned afr[4];
        {
            unsigned a = (unsigned)__cvta_generic_to_shared(
                &As[mBase + (lane & 15)][k0 + (lane >> 4) * 8]);
            ldm_x4(afr, a);
        }
#pragma unroll
        for (int np = 0; np < 4; np++) {
            unsigned bt[4];
            unsigned a = (unsigned)__cvta_generic_to_shared(
                &Bs[np * 16 + (lane & 7) + 8 * (lane >> 4)]
                   [k0 + ((lane >> 3) & 1) * 8]);
            ldm_x4(bt, a);
            mma_bf16(acc[np * 2 + 0], afr, bt[0], bt[1]);
            mma_bf16(acc[np * 2 + 1], afr, bt[2], bt[3]);
        }
    }

    // Fused epilogue. sim = dot*10; exp(sim) = exp2(dot*10*log2e).
    const float K10LOG2E = 14.4269504089f;
    int g = lane >> 2, tq = lane & 3;
    int riB = i0 + mBase + g;
    int cjB = j0 + tq * 2;
    float sumv = 0.f;
#pragma unroll
    for (int ni = 0; ni < 8; ni++) {
#pragma unroll
        for (int e = 0; e < 4; e++) {
            int ri = riB + ((e >> 1) ? 8 : 0);
            int cj = cjB + ni * 8 + (e & 1);
            if (ri >= nI || cj >= nJ) continue;
            if (mode == 0) {
                if (cj > ri) sumv += exp2f(acc[ni][e] * K10LOG2E);
            } else {
                float ex = exp2f(acc[ni][e] * K10LOG2E);
                sumv += __log2f(1.0f + ex);
            }
        }
    }

#pragma unroll
    for (int o = 16; o; o >>= 1)
        sumv += __shfl_down_sync(0xffffffffu, sumv, o);
    if (lane == 0) s_warp[warp] = sumv;
    __syncthreads();
    if (warp == 0) {
        float v = (lane < 8) ? s_warp[lane] : 0.f;
#pragma unroll
        for (int o = 4; o; o >>= 1)
            v += __shfl_down_sync(0xffffffffu, v, o);
        if (lane == 0) {
            if (mode == 0) atomicAdd(&g_pos[b], 2.0 * (double)v);  // symmetry
            else atomicAdd(&g_neg[b], (double)v * 0.6931471805599453);  // ln2
        }
    }
}

// ---------------------------------------------------------------------------
// Finalize scalar
// ---------------------------------------------------------------------------
__global__ void finalize_kernel(float* __restrict__ out) {
    int tid = threadIdx.x;
    double per = 0.0, vcnt = 0.0;
    if (tid < NB) {
        int nn = g_cnt[tid];
        int na = NN - nn;
        bool valid = (nn >= 10) && (na >= 5);
        double pc = (double)nn * (double)nn - (double)nn;
        double cc = (double)nn * (double)na;
        double pm = g_pos[tid] / (pc > 1.0 ? pc : 1.0);
        double pl = -log(pm + 1e-6);
        double nl = g_neg[tid] / (cc > 1.0 ? cc : 1.0);
        if (valid) { per = pl + nl; vcnt = 1.0; }
    }
    for (int o = 16; o; o >>= 1) {
        per += __shfl_down_sync(0xffffffffu, per, o);
        vcnt += __shfl_down_sync(0xffffffffu, vcnt, o);
    }
    if (tid == 0) out[0] = (float)(per / (vcnt > 1.0 ? vcnt : 1.0));
}

extern "C" void kernel_launch(void* const* d_in, const int* in_sizes, int n_in,
                              void* d_out, int out_size) {
    const float* feat = (const float*)d_in[0];   // [8,64,4000,1]
    const float* prob = (const float*)d_in[1];   // [8,1,4000,1]

    compact_kernel<<<NB, 256>>>(prob);
    normalize_kernel<<<(NB * NN + 255) / 256, 256>>>(feat);
    dim3 grid(2 * JT63, (NN + TI - 1) / TI, NB);   // (mode|jt, it, b)
    mma_loss_kernel<<<grid, 256>>>();
    finalize_kernel<<<1, 32>>>((float*)d_out);
}

// round 10
// speedup vs baseline: 1.5285x; 1.1898x over previous
#include <cuda_runtime.h>
#include <cuda_bf16.h>
#include <stdint.h>
#include <math.h>

#define NB 8
#define NC 64
#define NN 4000
#define TI 128          // i-tile
#define TJ 64           // j-tile
#define JT63 63         // ceil(4000/64) j-tiles per mode
#define SMSTRIDE 72     // 64 bf16 + 8 pad (144B rows; ldmatrix conflict-free)
#define PER 16          // indices per thread in compact (256*16 = 4096 >= NN)

// Scratch (device globals; no allocations allowed)
__device__ __nv_bfloat16 g_feat2[NB * NN * NC];  // normalized, COMPACTED order
__device__ int           g_pmap[NB * NN];        // orig idx -> p (normal) or ~pA (anomaly)
__device__ int           g_cnt[NB];
__device__ double        g_pos[NB];
__device__ double        g_neg[NB];

// ---------------------------------------------------------------------------
// Kernel 1: classify + position map via ONE block-scan (deterministic).
// ---------------------------------------------------------------------------
__global__ void compact_kernel(const float* __restrict__ prob) {
    int b = blockIdx.x;
    int tid = threadIdx.x;
    int lane = tid & 31, wid = tid >> 5;
    int start = tid * PER;

    const float* pb = prob + b * NN;
    unsigned mask = 0;
    int cN = 0;
#pragma unroll
    for (int k = 0; k < PER; k++) {
        int idx = start + k;
        if (idx < NN && pb[idx] < 0.5f) { mask |= (1u << k); cN++; }
    }
    int nv = (start < NN) ? min(PER, NN - start) : 0;
    int cA = nv - cN;

    int sNi = cN, sAi = cA;
#pragma unroll
    for (int o = 1; o < 32; o <<= 1) {
        int xn = __shfl_up_sync(0xffffffffu, sNi, o);
        int xa = __shfl_up_sync(0xffffffffu, sAi, o);
        if (lane >= o) { sNi += xn; sAi += xa; }
    }
    __shared__ int wN[8], wA[8];
    if (lane == 31) { wN[wid] = sNi; wA[wid] = sAi; }
    __syncthreads();
    int baseWN = 0, baseWA = 0, totN = 0;
    for (int w = 0; w < 8; w++) {
        if (w < wid) { baseWN += wN[w]; baseWA += wA[w]; }
        totN += wN[w];
    }
    int offN = baseWN + sNi - cN;
    int offA = baseWA + sAi - cA;

    int* pm = g_pmap + b * NN;
#pragma unroll
    for (int k = 0; k < PER; k++) {
        int idx = start + k;
        if (idx >= NN) break;
        if (mask & (1u << k)) pm[idx] = offN++;
        else                  pm[idx] = ~(offA++);
    }
    if (tid == 0) {
        g_cnt[b] = totN;
        g_pos[b] = 0.0;
        g_neg[b] = 0.0;
    }
}

// ---------------------------------------------------------------------------
// Kernel 2: row-normalize (fp32) -> bf16, writing to COMPACTED row position.
// ---------------------------------------------------------------------------
__global__ void normalize_kernel(const float* __restrict__ feat) {
    int row = blockIdx.x * blockDim.x + threadIdx.x;
    if (row >= NB * NN) return;
    int b = row / NN;
    int n = row - b * NN;
    const float* src = feat + (size_t)b * NC * NN + n;
    float v[NC];
    float ss = 0.f;
#pragma unroll
    for (int c = 0; c < NC; c++) {
        float x = src[(size_t)c * NN];
        v[c] = x;
        ss += x * x;
    }
    float inv = 1.0f / fmaxf(sqrtf(ss), 1e-12f);
    int pm = g_pmap[b * NN + n];
    int dstRow = (pm >= 0) ? pm : (g_cnt[b] + ~pm);
    __nv_bfloat16* dst = g_feat2 + ((size_t)b * NN + dstRow) * NC;
#pragma unroll
    for (int c = 0; c < NC; c++) dst[c] = __float2bfloat16(v[c] * inv);
}

// ---------------------------------------------------------------------------
// Merged fused GEMM + loss.
// mode 0: normal x normal, UPPER TRIANGLE ONLY (cj > ri), sum exp, x2 at end.
// mode 1: normal x anomaly (softplus).
// Epilogue has a fast path for interior tiles (no per-element predicates).
// ---------------------------------------------------------------------------
__device__ __forceinline__ void cpa16(unsigned dst, const void* src, bool valid) {
    int sz = valid ? 16 : 0;
    asm volatile("cp.async.cg.shared.global [%0], [%1], 16, %2;\n"
                 :: "r"(dst), "l"(src), "r"(sz));
}
__device__ __forceinline__ void ldm_x4(unsigned r[4], unsigned addr) {
    asm volatile("ldmatrix.sync.aligned.m8n8.x4.shared.b16 {%0,%1,%2,%3}, [%4];\n"
                 : "=r"(r[0]), "=r"(r[1]), "=r"(r[2]), "=r"(r[3]) : "r"(addr));
}
__device__ __forceinline__ void mma_bf16(float d[4], const unsigned a[4],
                                         unsigned b0, unsigned b1) {
    asm volatile(
        "mma.sync.aligned.m16n8k16.row.col.f32.bf16.bf16.f32 "
        "{%0,%1,%2,%3}, {%4,%5,%6,%7}, {%8,%9}, {%0,%1,%2,%3};\n"
        : "+f"(d[0]), "+f"(d[1]), "+f"(d[2]), "+f"(d[3])
        : "r"(a[0]), "r"(a[1]), "r"(a[2]), "r"(a[3]), "r"(b0), "r"(b1));
}

__global__ __launch_bounds__(256, 3) void mma_loss_kernel() {
    int b = blockIdx.z;
    int nI = g_cnt[b];
    int mode = (blockIdx.x >= JT63) ? 1 : 0;
    int jt = blockIdx.x - mode * JT63;
    int nJ = mode ? (NN - nI) : nI;
    int i0 = blockIdx.y * TI;
    int j0 = jt * TJ;
    if (i0 >= nI || j0 >= nJ) return;
    if (mode == 0 && (j0 + TJ - 1) <= i0) return;   // below diagonal: skip

    __shared__ __nv_bfloat16 As[TI][SMSTRIDE];
    __shared__ __nv_bfloat16 Bs[TJ][SMSTRIDE];
    __shared__ float s_warp[8];

    int tid = threadIdx.x;
    const __nv_bfloat16* Abase = g_feat2 + ((size_t)b * NN + i0) * NC;
    const __nv_bfloat16* Bbase =
        g_feat2 + ((size_t)b * NN + (mode ? nI : 0) + j0) * NC;

#pragma unroll
    for (int c = 0; c < 4; c++) {
        int chunk = tid + c * 256;
        int r = chunk >> 3, col = chunk & 7;
        unsigned dst = (unsigned)__cvta_generic_to_shared(&As[r][col * 8]);
        cpa16(dst, Abase + (size_t)r * NC + col * 8, (i0 + r) < nI);
    }
#pragma unroll
    for (int c = 0; c < 2; c++) {
        int chunk = tid + c * 256;
        int r = chunk >> 3, col = chunk & 7;
        unsigned dst = (unsigned)__cvta_generic_to_shared(&Bs[r][col * 8]);
        cpa16(dst, Bbase + (size_t)r * NC + col * 8, (j0 + r) < nJ);
    }
    asm volatile("cp.async.commit_group;\n");
    asm volatile("cp.async.wait_group 0;\n");
    __syncthreads();

    int warp = tid >> 5, lane = tid & 31;
    int mBase = warp * 16;               // warp tile 16 (M) x 64 (N)

    float acc[8][4];
#pragma unroll
    for (int ni = 0; ni < 8; ni++)
#pragma unroll
        for (int e = 0; e < 4; e++) acc[ni][e] = 0.f;

#pragma unroll
    for (int ks = 0; ks < 4; ks++) {
        int k0 = ks * 16;
        unsigned afr[4];
        {
            unsigned a = (unsigned)__cvta_generic_to_shared(
                &As[mBase + (lane & 15)][k0 + (lane >> 4) * 8]);
            ldm_x4(afr, a);
        }
#pragma unroll
        for (int np = 0; np < 4; np++) {
            unsigned bt[4];
            unsigned a = (unsigned)__cvta_generic_to_shared(
                &Bs[np * 16 + (lane & 7) + 8 * (lane >> 4)]
                   [k0 + ((lane >> 3) & 1) * 8]);
            ldm_x4(bt, a);
            mma_bf16(acc[np * 2 + 0], afr, bt[0], bt[1]);
            mma_bf16(acc[np * 2 + 1], afr, bt[2], bt[3]);
        }
    }

    // Fused epilogue. sim = dot*10; exp(sim) = exp2(dot*10*log2e).
    const float K10LOG2E = 14.4269504089f;
    int g = lane >> 2, tq = lane & 3;
    int riB = i0 + mBase + g;            // this lane's smaller row index
    int cjB = j0 + tq * 2;
    float sumv = 0.f;

    bool interior = ((i0 + TI) <= nI) && ((j0 + TJ) <= nJ);
    if (mode == 0) {
        if (interior && j0 >= i0 + TI) {
            // Strictly above diagonal, fully in range: unguarded exp chain.
#pragma unroll
            for (int ni = 0; ni < 8; ni++)
#pragma unroll
                for (int e = 0; e < 4; e++)
                    sumv += exp2f(acc[ni][e] * K10LOG2E);
        } else {
#pragma unroll
            for (int ni = 0; ni < 8; ni++) {
#pragma unroll
                for (int e = 0; e < 4; e++) {
                    int ri = riB + ((e >> 1) ? 8 : 0);
                    int cj = cjB + ni * 8 + (e & 1);
                    if (ri < nI && cj < nJ && cj > ri)
                        sumv += exp2f(acc[ni][e] * K10LOG2E);
                }
            }
        }
    } else {
        if (interior) {
            // Fully in range: unguarded softplus chain.
#pragma unroll
            for (int ni = 0; ni < 8; ni++)
#pragma unroll
                for (int e = 0; e < 4; e++)
                    sumv += __log2f(1.0f + exp2f(acc[ni][e] * K10LOG2E));
        } else {
#pragma unroll
            for (int ni = 0; ni < 8; ni++) {
#pragma unroll
                for (int e = 0; e < 4; e++) {
                    int ri = riB + ((e >> 1) ? 8 : 0);
                    int cj = cjB + ni * 8 + (e & 1);
                    if (ri < nI && cj < nJ)
                        sumv += __log2f(1.0f + exp2f(acc[ni][e] * K10LOG2E));
                }
            }
        }
    }

#pragma unroll
    for (int o = 16; o; o >>= 1)
        sumv += __shfl_down_sync(0xffffffffu, sumv, o);
    if (lane == 0) s_warp[warp] = sumv;
    __syncthreads();
    if (warp == 0) {
        float v = (lane < 8) ? s_warp[lane] : 0.f;
#pragma unroll
        for (int o = 4; o; o >>= 1)
            v += __shfl_down_sync(0xffffffffu, v, o);
        if (lane == 0) {
            if (mode == 0) atomicAdd(&g_pos[b], 2.0 * (double)v);  // symmetry
            else atomicAdd(&g_neg[b], (double)v * 0.6931471805599453);  // ln2
        }
    }
}

// ---------------------------------------------------------------------------
// Finalize scalar
// ---------------------------------------------------------------------------
__global__ void finalize_kernel(float* __restrict__ out) {
    int tid = threadIdx.x;
    double per = 0.0, vcnt = 0.0;
    if (tid < NB) {
        int nn = g_cnt[tid];
        int na = NN - nn;
        bool valid = (nn >= 10) && (na >= 5);
        double pc = (double)nn * (double)nn - (double)nn;
        double cc = (double)nn * (double)na;
        double pm = g_pos[tid] / (pc > 1.0 ? pc : 1.0);
        double pl = -log(pm + 1e-6);
        double nl = g_neg[tid] / (cc > 1.0 ? cc : 1.0);
        if (valid) { per = pl + nl; vcnt = 1.0; }
    }
    for (int o = 16; o; o >>= 1) {
        per += __shfl_down_sync(0xffffffffu, per, o);
        vcnt += __shfl_down_sync(0xffffffffu, vcnt, o);
    }
    if (tid == 0) out[0] = (float)(per / (vcnt > 1.0 ? vcnt : 1.0));
}

extern "C" void kernel_launch(void* const* d_in, const int* in_sizes, int n_in,
                              void* d_out, int out_size) {
    const float* feat = (const float*)d_in[0];   // [8,64,4000,1]
    const float* prob = (const float*)d_in[1];   // [8,1,4000,1]

    compact_kernel<<<NB, 256>>>(prob);
    normalize_kernel<<<(NB * NN + 255) / 256, 256>>>(feat);
    dim3 grid(2 * JT63, (NN + TI - 1) / TI, NB);   // (mode|jt, it, b)
    mma_loss_kernel<<<grid, 256>>>();
    finalize_kernel<<<1, 32>>>((float*)d_out);
}

// round 11
// speedup vs baseline: 1.7766x; 1.1623x over previous
#include <cuda_runtime.h>
#include <cuda_bf16.h>
#include <stdint.h>
#include <math.h>

#define NB 8
#define NC 64
#define NN 4000
#define TI 128          // i-tile rows
#define TJS 64          // j-subtile width
#define NSUB 2          // j-subtiles per block (block J strip = 128)
#define JT32 32         // ceil(4000/128) j-strips per mode
#define SMSTRIDE 72     // 64 bf16 + 8 pad (144B rows; ldmatrix conflict-free)
#define PER 16          // indices per thread in compact

// Scratch (device globals; no allocations allowed)
__device__ __nv_bfloat16 g_feat2[NB * NN * NC];  // normalized, COMPACTED order
__device__ int           g_pmap[NB * NN];
__device__ int           g_cnt[NB];
__device__ double        g_pos[NB];
__device__ double        g_neg[NB];

// ---------------------------------------------------------------------------
// Kernel 1: classify + position map via ONE block-scan (deterministic).
// ---------------------------------------------------------------------------
__global__ void compact_kernel(const float* __restrict__ prob) {
    int b = blockIdx.x;
    int tid = threadIdx.x;
    int lane = tid & 31, wid = tid >> 5;
    int start = tid * PER;

    const float* pb = prob + b * NN;
    unsigned mask = 0;
    int cN = 0;
#pragma unroll
    for (int k = 0; k < PER; k++) {
        int idx = start + k;
        if (idx < NN && pb[idx] < 0.5f) { mask |= (1u << k); cN++; }
    }
    int nv = (start < NN) ? min(PER, NN - start) : 0;
    int cA = nv - cN;

    int sNi = cN, sAi = cA;
#pragma unroll
    for (int o = 1; o < 32; o <<= 1) {
        int xn = __shfl_up_sync(0xffffffffu, sNi, o);
        int xa = __shfl_up_sync(0xffffffffu, sAi, o);
        if (lane >= o) { sNi += xn; sAi += xa; }
    }
    __shared__ int wN[8], wA[8];
    if (lane == 31) { wN[wid] = sNi; wA[wid] = sAi; }
    __syncthreads();
    int baseWN = 0, baseWA = 0, totN = 0;
    for (int w = 0; w < 8; w++) {
        if (w < wid) { baseWN += wN[w]; baseWA += wA[w]; }
        totN += wN[w];
    }
    int offN = baseWN + sNi - cN;
    int offA = baseWA + sAi - cA;

    int* pm = g_pmap + b * NN;
#pragma unroll
    for (int k = 0; k < PER; k++) {
        int idx = start + k;
        if (idx >= NN) break;
        if (mask & (1u << k)) pm[idx] = offN++;
        else                  pm[idx] = ~(offA++);
    }
    if (tid == 0) {
        g_cnt[b] = totN;
        g_pos[b] = 0.0;
        g_neg[b] = 0.0;
    }
}

// ---------------------------------------------------------------------------
// Kernel 2: row-normalize (fp32) -> bf16, writing to COMPACTED row position.
// ---------------------------------------------------------------------------
__global__ void normalize_kernel(const float* __restrict__ feat) {
    int row = blockIdx.x * blockDim.x + threadIdx.x;
    if (row >= NB * NN) return;
    int b = row / NN;
    int n = row - b * NN;
    const float* src = feat + (size_t)b * NC * NN + n;
    float v[NC];
    float ss = 0.f;
#pragma unroll
    for (int c = 0; c < NC; c++) {
        float x = src[(size_t)c * NN];
        v[c] = x;
        ss += x * x;
    }
    float inv = 1.0f / fmaxf(sqrtf(ss), 1e-12f);
    int pm = g_pmap[b * NN + n];
    int dstRow = (pm >= 0) ? pm : (g_cnt[b] + ~pm);
    __nv_bfloat16* dst = g_feat2 + ((size_t)b * NN + dstRow) * NC;
#pragma unroll
    for (int c = 0; c < NC; c++) dst[c] = __float2bfloat16(v[c] * inv);
}

// ---------------------------------------------------------------------------
// Merged fused GEMM + loss. Each block: one 128-row A tile x TWO 64-wide
// B subtiles (A smem reused). mode 0: upper triangle, sum exp, x2.
// mode 1: softplus. Interior-tile fast paths (no per-element predicates).
// ---------------------------------------------------------------------------
__device__ __forceinline__ void cpa16(unsigned dst, const void* src, bool valid) {
    int sz = valid ? 16 : 0;
    asm volatile("cp.async.cg.shared.global [%0], [%1], 16, %2;\n"
                 :: "r"(dst), "l"(src), "r"(sz));
}
__device__ __forceinline__ void ldm_x4(unsigned r[4], unsigned addr) {
    asm volatile("ldmatrix.sync.aligned.m8n8.x4.shared.b16 {%0,%1,%2,%3}, [%4];\n"
                 : "=r"(r[0]), "=r"(r[1]), "=r"(r[2]), "=r"(r[3]) : "r"(addr));
}
__device__ __forceinline__ void mma_bf16(float d[4], const unsigned a[4],
                                         unsigned b0, unsigned b1) {
    asm volatile(
        "mma.sync.aligned.m16n8k16.row.col.f32.bf16.bf16.f32 "
        "{%0,%1,%2,%3}, {%4,%5,%6,%7}, {%8,%9}, {%0,%1,%2,%3};\n"
        : "+f"(d[0]), "+f"(d[1]), "+f"(d[2]), "+f"(d[3])
        : "r"(a[0]), "r"(a[1]), "r"(a[2]), "r"(a[3]), "r"(b0), "r"(b1));
}

__global__ __launch_bounds__(256, 3) void mma_loss_kernel() {
    int b = blockIdx.z;
    int nI = g_cnt[b];
    int mode = (blockIdx.x >= JT32) ? 1 : 0;
    int jt = blockIdx.x - mode * JT32;
    int nJ = mode ? (NN - nI) : nI;
    int i0 = blockIdx.y * TI;
    int j0 = jt * (TJS * NSUB);
    if (i0 >= nI || j0 >= nJ) return;
    // mode 0: skip strips entirely below the diagonal.
    if (mode == 0 && (j0 + TJS * NSUB - 1) <= i0) return;

    __shared__ __nv_bfloat16 As[TI][SMSTRIDE];
    __shared__ __nv_bfloat16 Bs[NSUB][TJS][SMSTRIDE];
    __shared__ float s_warp[8];

    int tid = threadIdx.x;
    const __nv_bfloat16* Abase = g_feat2 + ((size_t)b * NN + i0) * NC;
    const __nv_bfloat16* Bbase =
        g_feat2 + ((size_t)b * NN + (mode ? nI : 0) + j0) * NC;

    // Fills: A = 1024 chunks (4/thread); B = 2 x 512 chunks (4/thread).
#pragma unroll
    for (int c = 0; c < 4; c++) {
        int chunk = tid + c * 256;
        int r = chunk >> 3, col = chunk & 7;
        unsigned dst = (unsigned)__cvta_generic_to_shared(&As[r][col * 8]);
        cpa16(dst, Abase + (size_t)r * NC + col * 8, (i0 + r) < nI);
    }
#pragma unroll
    for (int s = 0; s < NSUB; s++) {
#pragma unroll
        for (int c = 0; c < 2; c++) {
            int chunk = tid + c * 256;
            int r = chunk >> 3, col = chunk & 7;
            int jr = s * TJS + r;
            unsigned dst = (unsigned)__cvta_generic_to_shared(&Bs[s][r][col * 8]);
            cpa16(dst, Bbase + (size_t)jr * NC + col * 8, (j0 + jr) < nJ);
        }
    }
    asm volatile("cp.async.commit_group;\n");
    asm volatile("cp.async.wait_group 0;\n");
    __syncthreads();

    int warp = tid >> 5, lane = tid & 31;
    int mBase = warp * 16;               // warp tile 16 (M) x 64 (N)
    const float K10LOG2E = 14.4269504089f;
    int g = lane >> 2, tq = lane & 3;
    int riB = i0 + mBase + g;
    float sumv = 0.f;

#pragma unroll
    for (int sub = 0; sub < NSUB; sub++) {
        int j0s = j0 + sub * TJS;
        if (j0s >= nJ) break;
        if (mode == 0 && (j0s + TJS - 1) <= i0) continue;  // sub below diag

        float acc[8][4];
#pragma unroll
        for (int ni = 0; ni < 8; ni++)
#pragma unroll
            for (int e = 0; e < 4; e++) acc[ni][e] = 0.f;

#pragma unroll
        for (int ks = 0; ks < 4; ks++) {
            int k0 = ks * 16;
            unsigned afr[4];
            {
                unsigned a = (unsigned)__cvta_generic_to_shared(
                    &As[mBase + (lane & 15)][k0 + (lane >> 4) * 8]);
                ldm_x4(afr, a);
            }
#pragma unroll
            for (int np = 0; np < 4; np++) {
                unsigned bt[4];
                unsigned a = (unsigned)__cvta_generic_to_shared(
                    &Bs[sub][np * 16 + (lane & 7) + 8 * (lane >> 4)]
                       [k0 + ((lane >> 3) & 1) * 8]);
                ldm_x4(bt, a);
                mma_bf16(acc[np * 2 + 0], afr, bt[0], bt[1]);
                mma_bf16(acc[np * 2 + 1], afr, bt[2], bt[3]);
            }
        }

        int cjB = j0s + tq * 2;
        bool interior = ((i0 + TI) <= nI) && ((j0s + TJS) <= nJ);
        if (mode == 0) {
            if (interior && j0s >= i0 + TI) {
#pragma unroll
                for (int ni = 0; ni < 8; ni++)
#pragma unroll
                    for (int e = 0; e < 4; e++)
                        sumv += exp2f(acc[ni][e] * K10LOG2E);
            } else {
#pragma unroll
                for (int ni = 0; ni < 8; ni++) {
#pragma unroll
                    for (int e = 0; e < 4; e++) {
                        int ri = riB + ((e >> 1) ? 8 : 0);
                        int cj = cjB + ni * 8 + (e & 1);
                        if (ri < nI && cj < nJ && cj > ri)
                            sumv += exp2f(acc[ni][e] * K10LOG2E);
                    }
                }
            }
        } else {
            if (interior) {
#pragma unroll
                for (int ni = 0; ni < 8; ni++)
#pragma unroll
                    for (int e = 0; e < 4; e++)
                        sumv += __log2f(1.0f + exp2f(acc[ni][e] * K10LOG2E));
            } else {
#pragma unroll
                for (int ni = 0; ni < 8; ni++) {
#pragma unroll
                    for (int e = 0; e < 4; e++) {
                        int ri = riB + ((e >> 1) ? 8 : 0);
                        int cj = cjB + ni * 8 + (e & 1);
                        if (ri < nI && cj < nJ)
                            sumv += __log2f(1.0f + exp2f(acc[ni][e] * K10LOG2E));
                    }
                }
            }
        }
    }

#pragma unroll
    for (int o = 16; o; o >>= 1)
        sumv += __shfl_down_sync(0xffffffffu, sumv, o);
    if (lane == 0) s_warp[warp] = sumv;
    __syncthreads();
    if (warp == 0) {
        float v = (lane < 8) ? s_warp[lane] : 0.f;
#pragma unroll
        for (int o = 4; o; o >>= 1)
            v += __shfl_down_sync(0xffffffffu, v, o);
        if (lane == 0) {
            if (mode == 0) atomicAdd(&g_pos[b], 2.0 * (double)v);  // symmetry
            else atomicAdd(&g_neg[b], (double)v * 0.6931471805599453);  // ln2
        }
    }
}

// ---------------------------------------------------------------------------
// Finalize scalar
// ---------------------------------------------------------------------------
__global__ void finalize_kernel(float* __restrict__ out) {
    int tid = threadIdx.x;
    double per = 0.0, vcnt = 0.0;
    if (tid < NB) {
        int nn = g_cnt[tid];
        int na = NN - nn;
        bool valid = (nn >= 10) && (na >= 5);
        double pc = (double)nn * (double)nn - (double)nn;
        double cc = (double)nn * (double)na;
        double pm = g_pos[tid] / (pc > 1.0 ? pc : 1.0);
        double pl = -log(pm + 1e-6);
        double nl = g_neg[tid] / (cc > 1.0 ? cc : 1.0);
        if (valid) { per = pl + nl; vcnt = 1.0; }
    }
    for (int o = 16; o; o >>= 1) {
        per += __shfl_down_sync(0xffffffffu, per, o);
        vcnt += __shfl_down_sync(0xffffffffu, vcnt, o);
    }
    if (tid == 0) out[0] = (float)(per / (vcnt > 1.0 ? vcnt : 1.0));
}

extern "C" void kernel_launch(void* const* d_in, const int* in_sizes, int n_in,
                              void* d_out, int out_size) {
    const float* feat = (const float*)d_in[0];   // [8,64,4000,1]
    const float* prob = (const float*)d_in[1];   // [8,1,4000,1]

    compact_kernel<<<NB, 256>>>(prob);
    normalize_kernel<<<(NB * NN + 255) / 256, 256>>>(feat);
    dim3 grid(2 * JT32, (NN + TI - 1) / TI, NB);   // (mode|jstrip, it, b)
    mma_loss_kernel<<<grid, 256>>>();
    finalize_kernel<<<1, 32>>>((float*)d_out);
}

// round 13
// speedup vs baseline: 1.8732x; 1.0544x over previous
#include <cuda_runtime.h>
#include <cuda_bf16.h>
#include <stdint.h>
#include <math.h>

#define NB 8
#define NC 64
#define NN 4000
#define TI 128          // i-tile rows
#define TJS 64          // j-subtile width
#define NSUB 3          // j-subtiles per block (strip = 192; smem 46.1KB < 48KB)
#define JTS 21          // ceil(4000/192) j-strips per mode
#define SMSTRIDE 72     // 64 bf16 + 8 pad (144B rows; ldmatrix conflict-free)
#define PER 16          // indices per thread in compact

// Scratch (device globals; no allocations allowed)
__device__ __nv_bfloat16 g_feat2[NB * NN * NC];  // normalized, COMPACTED order
__device__ int           g_pmap[NB * NN];
__device__ int           g_cnt[NB];
__device__ double        g_pos[NB];
__device__ double        g_neg[NB];

// ---------------------------------------------------------------------------
// Kernel 1: classify + position map via ONE block-scan (deterministic).
// ---------------------------------------------------------------------------
__global__ void compact_kernel(const float* __restrict__ prob) {
    int b = blockIdx.x;
    int tid = threadIdx.x;
    int lane = tid & 31, wid = tid >> 5;
    int start = tid * PER;

    const float* pb = prob + b * NN;
    unsigned mask = 0;
    int cN = 0;
#pragma unroll
    for (int k = 0; k < PER; k++) {
        int idx = start + k;
        if (idx < NN && pb[idx] < 0.5f) { mask |= (1u << k); cN++; }
    }
    int nv = (start < NN) ? min(PER, NN - start) : 0;
    int cA = nv - cN;

    int sNi = cN, sAi = cA;
#pragma unroll
    for (int o = 1; o < 32; o <<= 1) {
        int xn = __shfl_up_sync(0xffffffffu, sNi, o);
        int xa = __shfl_up_sync(0xffffffffu, sAi, o);
        if (lane >= o) { sNi += xn; sAi += xa; }
    }
    __shared__ int wN[8], wA[8];
    if (lane == 31) { wN[wid] = sNi; wA[wid] = sAi; }
    __syncthreads();
    int baseWN = 0, baseWA = 0, totN = 0;
    for (int w = 0; w < 8; w++) {
        if (w < wid) { baseWN += wN[w]; baseWA += wA[w]; }
        totN += wN[w];
    }
    int offN = baseWN + sNi - cN;
    int offA = baseWA + sAi - cA;

    int* pm = g_pmap + b * NN;
#pragma unroll
    for (int k = 0; k < PER; k++) {
        int idx = start + k;
        if (idx >= NN) break;
        if (mask & (1u << k)) pm[idx] = offN++;
        else                  pm[idx] = ~(offA++);
    }
    if (tid == 0) {
        g_cnt[b] = totN;
        g_pos[b] = 0.0;
        g_neg[b] = 0.0;
    }
}

// ---------------------------------------------------------------------------
// Kernel 2: row-normalize (fp32) -> bf16, writing to COMPACTED row position.
// ---------------------------------------------------------------------------
__global__ void normalize_kernel(const float* __restrict__ feat) {
    int row = blockIdx.x * blockDim.x + threadIdx.x;
    if (row >= NB * NN) return;
    int b = row / NN;
    int n = row - b * NN;
    const float* src = feat + (size_t)b * NC * NN + n;
    float v[NC];
    float ss = 0.f;
#pragma unroll
    for (int c = 0; c < NC; c++) {
        float x = src[(size_t)c * NN];
        v[c] = x;
        ss += x * x;
    }
    float inv = 1.0f / fmaxf(sqrtf(ss), 1e-12f);
    int pm = g_pmap[b * NN + n];
    int dstRow = (pm >= 0) ? pm : (g_cnt[b] + ~pm);
    __nv_bfloat16* dst = g_feat2 + ((size_t)b * NN + dstRow) * NC;
#pragma unroll
    for (int c = 0; c < NC; c++) dst[c] = __float2bfloat16(v[c] * inv);
}

// ---------------------------------------------------------------------------
// Merged fused GEMM + loss. Each block: one 128-row A tile x THREE 64-wide
// B subtiles (A smem reused). mode 0: upper triangle, sum exp, x2.
// mode 1: softplus. Interior-tile fast paths (no per-element predicates).
// ---------------------------------------------------------------------------
__device__ __forceinline__ void cpa16(unsigned dst, const void* src, bool valid) {
    int sz = valid ? 16 : 0;
    asm volatile("cp.async.cg.shared.global [%0], [%1], 16, %2;\n"
                 :: "r"(dst), "l"(src), "r"(sz));
}
__device__ __forceinline__ void ldm_x4(unsigned r[4], unsigned addr) {
    asm volatile("ldmatrix.sync.aligned.m8n8.x4.shared.b16 {%0,%1,%2,%3}, [%4];\n"
                 : "=r"(r[0]), "=r"(r[1]), "=r"(r[2]), "=r"(r[3]) : "r"(addr));
}
__device__ __forceinline__ void mma_bf16(float d[4], const unsigned a[4],
                                         unsigned b0, unsigned b1) {
    asm volatile(
        "mma.sync.aligned.m16n8k16.row.col.f32.bf16.bf16.f32 "
        "{%0,%1,%2,%3}, {%4,%5,%6,%7}, {%8,%9}, {%0,%1,%2,%3};\n"
        : "+f"(d[0]), "+f"(d[1]), "+f"(d[2]), "+f"(d[3])
        : "r"(a[0]), "r"(a[1]), "r"(a[2]), "r"(a[3]), "r"(b0), "r"(b1));
}

__global__ __launch_bounds__(256, 3) void mma_loss_kernel() {
    int b = blockIdx.z;
    int nI = g_cnt[b];
    int mode = (blockIdx.x >= JTS) ? 1 : 0;
    int jt = blockIdx.x - mode * JTS;
    int nJ = mode ? (NN - nI) : nI;
    int i0 = blockIdx.y * TI;
    int j0 = jt * (TJS * NSUB);
    if (i0 >= nI || j0 >= nJ) return;
    // mode 0: skip strips entirely below the diagonal.
    if (mode == 0 && (j0 + TJS * NSUB - 1) <= i0) return;

    __shared__ __nv_bfloat16 As[TI][SMSTRIDE];
    __shared__ __nv_bfloat16 Bs[NSUB][TJS][SMSTRIDE];
    __shared__ float s_warp[8];

    int tid = threadIdx.x;
    const __nv_bfloat16* Abase = g_feat2 + ((size_t)b * NN + i0) * NC;
    const __nv_bfloat16* Bbase =
        g_feat2 + ((size_t)b * NN + (mode ? nI : 0) + j0) * NC;

    // Fills: A = 1024 chunks (4/thread); B = 3 x 512 chunks (6/thread).
#pragma unroll
    for (int c = 0; c < 4; c++) {
        int chunk = tid + c * 256;
        int r = chunk >> 3, col = chunk & 7;
        unsigned dst = (unsigned)__cvta_generic_to_shared(&As[r][col * 8]);
        cpa16(dst, Abase + (size_t)r * NC + col * 8, (i0 + r) < nI);
    }
#pragma unroll
    for (int s = 0; s < NSUB; s++) {
#pragma unroll
        for (int c = 0; c < 2; c++) {
            int chunk = tid + c * 256;
            int r = chunk >> 3, col = chunk & 7;
            int jr = s * TJS + r;
            unsigned dst = (unsigned)__cvta_generic_to_shared(&Bs[s][r][col * 8]);
            cpa16(dst, Bbase + (size_t)jr * NC + col * 8, (j0 + jr) < nJ);
        }
    }
    asm volatile("cp.async.commit_group;\n");
    asm volatile("cp.async.wait_group 0;\n");
    __syncthreads();

    int warp = tid >> 5, lane = tid & 31;
    int mBase = warp * 16;               // warp tile 16 (M) x 64 (N)
    const float K10LOG2E = 14.4269504089f;
    int g = lane >> 2, tq = lane & 3;
    int riB = i0 + mBase + g;
    float sumv = 0.f;

#pragma unroll
    for (int sub = 0; sub < NSUB; sub++) {
        int j0s = j0 + sub * TJS;
        if (j0s >= nJ) break;
        if (mode == 0 && (j0s + TJS - 1) <= i0) continue;  // sub below diag

        float acc[8][4];
#pragma unroll
        for (int ni = 0; ni < 8; ni++)
#pragma unroll
            for (int e = 0; e < 4; e++) acc[ni][e] = 0.f;

#pragma unroll
        for (int ks = 0; ks < 4; ks++) {
            int k0 = ks * 16;
            unsigned afr[4];
            {
                unsigned a = (unsigned)__cvta_generic_to_shared(
                    &As[mBase + (lane & 15)][k0 + (lane >> 4) * 8]);
                ldm_x4(afr, a);
            }
#pragma unroll
            for (int np = 0; np < 4; np++) {
                unsigned bt[4];
                unsigned a = (unsigned)__cvta_generic_to_shared(
                    &Bs[sub][np * 16 + (lane & 7) + 8 * (lane >> 4)]
                       [k0 + ((lane >> 3) & 1) * 8]);
                ldm_x4(bt, a);
                mma_bf16(acc[np * 2 + 0], afr, bt[0], bt[1]);
                mma_bf16(acc[np * 2 + 1], afr, bt[2], bt[3]);
            }
        }

        int cjB = j0s + tq * 2;
        bool interior = ((i0 + TI) <= nI) && ((j0s + TJS) <= nJ);
        if (mode == 0) {
            if (interior && j0s >= i0 + TI) {
#pragma unroll
                for (int ni = 0; ni < 8; ni++)
#pragma unroll
                    for (int e = 0; e < 4; e++)
                        sumv += exp2f(acc[ni][e] * K10LOG2E);
            } else {
#pragma unroll
                for (int ni = 0; ni < 8; ni++) {
#pragma unroll
                    for (int e = 0; e < 4; e++) {
                        int ri = riB + ((e >> 1) ? 8 : 0);
                        int cj = cjB + ni * 8 + (e & 1);
                        if (ri < nI && cj < nJ && cj > ri)
                            sumv += exp2f(acc[ni][e] * K10LOG2E);
                    }
                }
            }
        } else {
            if (interior) {
#pragma unroll
                for (int ni = 0; ni < 8; ni++)
#pragma unroll
                    for (int e = 0; e < 4; e++)
                        sumv += __log2f(1.0f + exp2f(acc[ni][e] * K10LOG2E));
            } else {
#pragma unroll
                for (int ni = 0; ni < 8; ni++) {
#pragma unroll
                    for (int e = 0; e < 4; e++) {
                        int ri = riB + ((e >> 1) ? 8 : 0);
                        int cj = cjB + ni * 8 + (e & 1);
                        if (ri < nI && cj < nJ)
                            sumv += __log2f(1.0f + exp2f(acc[ni][e] * K10LOG2E));
                    }
                }
            }
        }
    }

#pragma unroll
    for (int o = 16; o; o >>= 1)
        sumv += __shfl_down_sync(0xffffffffu, sumv, o);
    if (lane == 0) s_warp[warp] = sumv;
    __syncthreads();
    if (warp == 0) {
        float v = (lane < 8) ? s_warp[lane] : 0.f;
#pragma unroll
        for (int o = 4; o; o >>= 1)
            v += __shfl_down_sync(0xffffffffu, v, o);
        if (lane == 0) {
            if (mode == 0) atomicAdd(&g_pos[b], 2.0 * (double)v);  // symmetry
            else atomicAdd(&g_neg[b], (double)v * 0.6931471805599453);  // ln2
        }
    }
}

// ---------------------------------------------------------------------------
// Finalize scalar
// ---------------------------------------------------------------------------
__global__ void finalize_kernel(float* __restrict__ out) {
    int tid = threadIdx.x;
    double per = 0.0, vcnt = 0.0;
    if (tid < NB) {
        int nn = g_cnt[tid];
        int na = NN - nn;
        bool valid = (nn >= 10) && (na >= 5);
        double pc = (double)nn * (double)nn - (double)nn;
        double cc = (double)nn * (double)na;
        double pm = g_pos[tid] / (pc > 1.0 ? pc : 1.0);
        double pl = -log(pm + 1e-6);
        double nl = g_neg[tid] / (cc > 1.0 ? cc : 1.0);
        if (valid) { per = pl + nl; vcnt = 1.0; }
    }
    for (int o = 16; o; o >>= 1) {
        per += __shfl_down_sync(0xffffffffu, per, o);
        vcnt += __shfl_down_sync(0xffffffffu, vcnt, o);
    }
    if (tid == 0) out[0] = (float)(per / (vcnt > 1.0 ? vcnt : 1.0));
}

extern "C" void kernel_launch(void* const* d_in, const int* in_sizes, int n_in,
                              void* d_out, int out_size) {
    const float* feat = (const float*)d_in[0];   // [8,64,4000,1]
    const float* prob = (const float*)d_in[1];   // [8,1,4000,1]

    compact_kernel<<<NB, 256>>>(prob);
    normalize_kernel<<<(NB * NN + 255) / 256, 256>>>(feat);
    dim3 grid(2 * JTS, (NN + TI - 1) / TI, NB);   // (mode|jstrip, it, b)
    mma_loss_kernel<<<grid, 256>>>();
    finalize_kernel<<<1, 32>>>((float*)d_out);
}

// round 14
// speedup vs baseline: 2.0362x; 1.0870x over previous
#include <cuda_runtime.h>
#include <cuda_bf16.h>
#include <stdint.h>
#include <math.h>

#define NB 8
#define NC 64
#define NN 4000
#define TI 128          // i-tile rows
#define TJS 64          // j-subtile width
#define NSUB 3          // j-subtiles per block (strip = 192; smem 46.1KB < 48KB)
#define JTS 21          // ceil(4000/192) j-strips per mode
#define SMSTRIDE 72     // 64 bf16 + 8 pad (144B rows; ldmatrix conflict-free)
#define PER 16          // indices per thread in compact

// Scratch (device globals; no allocations allowed)
__device__ __nv_bfloat16 g_feat2[NB * NN * NC];  // normalized, COMPACTED order
__device__ int           g_pmap[NB * NN];
__device__ int           g_cnt[NB];
__device__ double        g_pos[NB];
__device__ double        g_neg[NB];

// ---------------------------------------------------------------------------
// Kernel 1: classify + position map via ONE block-scan (deterministic).
// ---------------------------------------------------------------------------
__global__ void compact_kernel(const float* __restrict__ prob) {
    int b = blockIdx.x;
    int tid = threadIdx.x;
    int lane = tid & 31, wid = tid >> 5;
    int start = tid * PER;

    const float* pb = prob + b * NN;
    unsigned mask = 0;
    int cN = 0;
#pragma unroll
    for (int k = 0; k < PER; k++) {
        int idx = start + k;
        if (idx < NN && pb[idx] < 0.5f) { mask |= (1u << k); cN++; }
    }
    int nv = (start < NN) ? min(PER, NN - start) : 0;
    int cA = nv - cN;

    int sNi = cN, sAi = cA;
#pragma unroll
    for (int o = 1; o < 32; o <<= 1) {
        int xn = __shfl_up_sync(0xffffffffu, sNi, o);
        int xa = __shfl_up_sync(0xffffffffu, sAi, o);
        if (lane >= o) { sNi += xn; sAi += xa; }
    }
    __shared__ int wN[8], wA[8];
    if (lane == 31) { wN[wid] = sNi; wA[wid] = sAi; }
    __syncthreads();
    int baseWN = 0, baseWA = 0, totN = 0;
    for (int w = 0; w < 8; w++) {
        if (w < wid) { baseWN += wN[w]; baseWA += wA[w]; }
        totN += wN[w];
    }
    int offN = baseWN + sNi - cN;
    int offA = baseWA + sAi - cA;

    int* pm = g_pmap + b * NN;
#pragma unroll
    for (int k = 0; k < PER; k++) {
        int idx = start + k;
        if (idx >= NN) break;
        if (mask & (1u << k)) pm[idx] = offN++;
        else                  pm[idx] = ~(offA++);
    }
    if (tid == 0) {
        g_cnt[b] = totN;
        g_pos[b] = 0.0;
        g_neg[b] = 0.0;
    }
}

// ---------------------------------------------------------------------------
// Kernel 2: row-normalize (fp32) -> bf16, writing to COMPACTED row position.
// ---------------------------------------------------------------------------
__global__ void normalize_kernel(const float* __restrict__ feat) {
    int row = blockIdx.x * blockDim.x + threadIdx.x;
    if (row >= NB * NN) return;
    int b = row / NN;
    int n = row - b * NN;
    const float* src = feat + (size_t)b * NC * NN + n;
    float v[NC];
    float ss = 0.f;
#pragma unroll
    for (int c = 0; c < NC; c++) {
        float x = src[(size_t)c * NN];
        v[c] = x;
        ss += x * x;
    }
    float inv = 1.0f / fmaxf(sqrtf(ss), 1e-12f);
    int pm = g_pmap[b * NN + n];
    int dstRow = (pm >= 0) ? pm : (g_cnt[b] + ~pm);
    __nv_bfloat16* dst = g_feat2 + ((size_t)b * NN + dstRow) * NC;
#pragma unroll
    for (int c = 0; c < NC; c++) dst[c] = __float2bfloat16(v[c] * inv);
}

// ---------------------------------------------------------------------------
// Merged fused GEMM + loss. Each block: one 128-row A tile x THREE 64-wide
// B subtiles (A smem reused). mode 0: upper triangle, sum exp, x2.
// mode 1: softplus via 4-way log-product pairing (1.25 MUFU/elem).
// ---------------------------------------------------------------------------
__device__ __forceinline__ void cpa16(unsigned dst, const void* src, bool valid) {
    int sz = valid ? 16 : 0;
    asm volatile("cp.async.cg.shared.global [%0], [%1], 16, %2;\n"
                 :: "r"(dst), "l"(src), "r"(sz));
}
__device__ __forceinline__ void ldm_x4(unsigned r[4], unsigned addr) {
    asm volatile("ldmatrix.sync.aligned.m8n8.x4.shared.b16 {%0,%1,%2,%3}, [%4];\n"
                 : "=r"(r[0]), "=r"(r[1]), "=r"(r[2]), "=r"(r[3]) : "r"(addr));
}
__device__ __forceinline__ void mma_bf16(float d[4], const unsigned a[4],
                                         unsigned b0, unsigned b1) {
    asm volatile(
        "mma.sync.aligned.m16n8k16.row.col.f32.bf16.bf16.f32 "
        "{%0,%1,%2,%3}, {%4,%5,%6,%7}, {%8,%9}, {%0,%1,%2,%3};\n"
        : "+f"(d[0]), "+f"(d[1]), "+f"(d[2]), "+f"(d[3])
        : "r"(a[0]), "r"(a[1]), "r"(a[2]), "r"(a[3]), "r"(b0), "r"(b1));
}

__global__ __launch_bounds__(256, 3) void mma_loss_kernel() {
    int b = blockIdx.z;
    int nI = g_cnt[b];
    int mode = (blockIdx.x >= JTS) ? 1 : 0;
    int jt = blockIdx.x - mode * JTS;
    int nJ = mode ? (NN - nI) : nI;
    int i0 = blockIdx.y * TI;
    int j0 = jt * (TJS * NSUB);
    if (i0 >= nI || j0 >= nJ) return;
    // mode 0: skip strips entirely below the diagonal.
    if (mode == 0 && (j0 + TJS * NSUB - 1) <= i0) return;

    __shared__ __nv_bfloat16 As[TI][SMSTRIDE];
    __shared__ __nv_bfloat16 Bs[NSUB][TJS][SMSTRIDE];
    __shared__ float s_warp[8];

    int tid = threadIdx.x;
    const __nv_bfloat16* Abase = g_feat2 + ((size_t)b * NN + i0) * NC;
    const __nv_bfloat16* Bbase =
        g_feat2 + ((size_t)b * NN + (mode ? nI : 0) + j0) * NC;

    // Fills: A = 1024 chunks (4/thread); B = 3 x 512 chunks (6/thread).
#pragma unroll
    for (int c = 0; c < 4; c++) {
        int chunk = tid + c * 256;
        int r = chunk >> 3, col = chunk & 7;
        unsigned dst = (unsigned)__cvta_generic_to_shared(&As[r][col * 8]);
        cpa16(dst, Abase + (size_t)r * NC + col * 8, (i0 + r) < nI);
    }
#pragma unroll
    for (int s = 0; s < NSUB; s++) {
#pragma unroll
        for (int c = 0; c < 2; c++) {
            int chunk = tid + c * 256;
            int r = chunk >> 3, col = chunk & 7;
            int jr = s * TJS + r;
            unsigned dst = (unsigned)__cvta_generic_to_shared(&Bs[s][r][col * 8]);
            cpa16(dst, Bbase + (size_t)jr * NC + col * 8, (j0 + jr) < nJ);
        }
    }
    asm volatile("cp.async.commit_group;\n");
    asm volatile("cp.async.wait_group 0;\n");
    __syncthreads();

    int warp = tid >> 5, lane = tid & 31;
    int mBase = warp * 16;               // warp tile 16 (M) x 64 (N)
    const float K10LOG2E = 14.4269504089f;
    int g = lane >> 2, tq = lane & 3;
    int riB = i0 + mBase + g;
    float sumv = 0.f;                    // mode0: sum exp; mode1: sum log2 terms

#pragma unroll
    for (int sub = 0; sub < NSUB; sub++) {
        int j0s = j0 + sub * TJS;
        if (j0s >= nJ) break;
        if (mode == 0 && (j0s + TJS - 1) <= i0) continue;  // sub below diag

        float acc[8][4];
#pragma unroll
        for (int ni = 0; ni < 8; ni++)
#pragma unroll
            for (int e = 0; e < 4; e++) acc[ni][e] = 0.f;

#pragma unroll
        for (int ks = 0; ks < 4; ks++) {
            int k0 = ks * 16;
            unsigned afr[4];
            {
                unsigned a = (unsigned)__cvta_generic_to_shared(
                    &As[mBase + (lane & 15)][k0 + (lane >> 4) * 8]);
                ldm_x4(afr, a);
            }
#pragma unroll
            for (int np = 0; np < 4; np++) {
                unsigned bt[4];
                unsigned a = (unsigned)__cvta_generic_to_shared(
                    &Bs[sub][np * 16 + (lane & 7) + 8 * (lane >> 4)]
                       [k0 + ((lane >> 3) & 1) * 8]);
                ldm_x4(bt, a);
                mma_bf16(acc[np * 2 + 0], afr, bt[0], bt[1]);
                mma_bf16(acc[np * 2 + 1], afr, bt[2], bt[3]);
            }
        }

        int cjB = j0s + tq * 2;
        bool interior = ((i0 + TI) <= nI) && ((j0s + TJS) <= nJ);
        if (mode == 0) {
            if (interior && j0s >= i0 + TI) {
#pragma unroll
                for (int ni = 0; ni < 8; ni++)
#pragma unroll
                    for (int e = 0; e < 4; e++)
                        sumv += exp2f(acc[ni][e] * K10LOG2E);
            } else {
#pragma unroll
                for (int ni = 0; ni < 8; ni++) {
#pragma unroll
                    for (int e = 0; e < 4; e++) {
                        int ri = riB + ((e >> 1) ? 8 : 0);
                        int cj = cjB + ni * 8 + (e & 1);
                        if (ri < nI && cj < nJ && cj > ri)
                            sumv += exp2f(acc[ni][e] * K10LOG2E);
                    }
                }
            }
        } else {
            // softplus sum via 4-way log-product:
            //   sum log2(1+ex_e) = log2( prod_e (1+ex_e) )
            // factors <= 1+2^14.43 => 4-way product <= 2.4e17, safe in fp32.
            if (interior) {
#pragma unroll
                for (int ni = 0; ni < 8; ni++) {
                    float p = 1.0f;
#pragma unroll
                    for (int e = 0; e < 4; e++)
                        p *= 1.0f + exp2f(acc[ni][e] * K10LOG2E);
                    sumv += __log2f(p);
                }
            } else {
#pragma unroll
                for (int ni = 0; ni < 8; ni++) {
                    float p = 1.0f;
#pragma unroll
                    for (int e = 0; e < 4; e++) {
                        int ri = riB + ((e >> 1) ? 8 : 0);
                        int cj = cjB + ni * 8 + (e & 1);
                        float ex = exp2f(acc[ni][e] * K10LOG2E);  // acc finite
                        bool v = (ri < nI) && (cj < nJ);
                        p *= v ? (1.0f + ex) : 1.0f;
                    }
                    sumv += __log2f(p);
                }
            }
        }
    }

#pragma unroll
    for (int o = 16; o; o >>= 1)
        sumv += __shfl_down_sync(0xffffffffu, sumv, o);
    if (lane == 0) s_warp[warp] = sumv;
    __syncthreads();
    if (warp == 0) {
        float v = (lane < 8) ? s_warp[lane] : 0.f;
#pragma unroll
        for (int o = 4; o; o >>= 1)
            v += __shfl_down_sync(0xffffffffu, v, o);
        if (lane == 0) {
            if (mode == 0) atomicAdd(&g_pos[b], 2.0 * (double)v);  // symmetry
            else atomicAdd(&g_neg[b], (double)v * 0.6931471805599453);  // ln2
        }
    }
}

// ---------------------------------------------------------------------------
// Finalize scalar
// ---------------------------------------------------------------------------
__global__ void finalize_kernel(float* __restrict__ out) {
    int tid = threadIdx.x;
    double per = 0.0, vcnt = 0.0;
    if (tid < NB) {
        int nn = g_cnt[tid];
        int na = NN - nn;
        bool valid = (nn >= 10) && (na >= 5);
        double pc = (double)nn * (double)nn - (double)nn;
        double cc = (double)nn * (double)na;
        double pm = g_pos[tid] / (pc > 1.0 ? pc : 1.0);
        double pl = -log(pm + 1e-6);
        double nl = g_neg[tid] / (cc > 1.0 ? cc : 1.0);
        if (valid) { per = pl + nl; vcnt = 1.0; }
    }
    for (int o = 16; o; o >>= 1) {
        per += __shfl_down_sync(0xffffffffu, per, o);
        vcnt += __shfl_down_sync(0xffffffffu, vcnt, o);
    }
    if (tid == 0) out[0] = (float)(per / (vcnt > 1.0 ? vcnt : 1.0));
}

extern "C" void kernel_launch(void* const* d_in, const int* in_sizes, int n_in,
                              void* d_out, int out_size) {
    const float* feat = (const float*)d_in[0];   // [8,64,4000,1]
    const float* prob = (const float*)d_in[1];   // [8,1,4000,1]

    compact_kernel<<<NB, 256>>>(prob);
    normalize_kernel<<<(NB * NN + 255) / 256, 256>>>(feat);
    dim3 grid(2 * JTS, (NN + TI - 1) / TI, NB);   // (mode|jstrip, it, b)
    mma_loss_kernel<<<grid, 256>>>();
    finalize_kernel<<<1, 32>>>((float*)d_out);
}